// round 15
// baseline (speedup 1.0000x reference)
#include <cuda_runtime.h>
#include <cuda_bf16.h>
#include <cstdint>

// eeg_input [16, 32, 1000, 64] fp32 -> per (b,w) slab: 64x1000 transpose of 1000x64.
//   out[bw][c*1000 + t] = in[bw][t*64 + c]
// Tail (out_size - PATCH_ELEMS == 640, f32): channel = i/5, time = i%5, i in [0,320).

#define N_BW   512
#define T_DIM  1000
#define C_DIM  64
#define PATCH_ELEMS (N_BW * T_DIM * C_DIM)   // 32,768,000 floats

#define TT     64                  // time rows per tile (full 64-channel width)
#define PAD    68                  // floats per smem row: 272B, 16B-aligned for cp.async
#define NTILE  16                  // t-tiles per slab
#define NTILES (N_BW * NTILE)      // 8192 tiles
#define GRID   888                 // persistent CTAs (~6/SM)

__device__ unsigned int g_tile_ctr;

__device__ __forceinline__ void cp_async16(uint32_t dst_smem, const void* src) {
    asm volatile("cp.async.cg.shared.global [%0], [%1], 16;\n"
                 :: "r"(dst_smem), "l"(src) : "memory");
}
__device__ __forceinline__ void cp_commit() {
    asm volatile("cp.async.commit_group;\n" ::: "memory");
}
__device__ __forceinline__ void cp_wait1() {
    asm volatile("cp.async.wait_group 1;\n" ::: "memory");
}

// Persistent double-buffered transpose: while the store phase drains buffer `cb`,
// cp.async stages the next tile into buffer `cb^1` -> reads always in flight.
__global__ __launch_bounds__(256) void labram_transpose_pipe_kernel(
    const float* __restrict__ in, float* __restrict__ out, int tail_mode)
{
    __shared__ float    buf[2][TT * PAD];
    __shared__ unsigned s_t[2];

    const int tid = threadIdx.x;

    // ---- Index tail (CTA 0, once) ----
    if (tail_mode != 0 && blockIdx.x == 0) {
        for (int i = tid; i < 320; i += 256) {
            if (tail_mode == 1) {              // float32-encoded indices
                out[PATCH_ELEMS + i]       = (float)(i / 5);
                out[PATCH_ELEMS + 320 + i] = (float)(i % 5);
            } else {                            // raw int64 indices
                long long* t64 = (long long*)(out + PATCH_ELEMS);
                t64[i]       = (long long)(i / 5);
                t64[320 + i] = (long long)(i % 5);
            }
        }
    }

    // ---- Grab first two tiles ----
    if (tid == 0) {
        s_t[0] = atomicAdd(&g_tile_ctr, 1u);
        s_t[1] = atomicAdd(&g_tile_ctr, 1u);
    }
    __syncthreads();

    // Per-thread load mapping (tile-invariant): 4 x 16B, 512B contiguous per warp.
    int tl[4], m[4];
    #pragma unroll
    for (int j = 0; j < 4; ++j) {
        const int idx = tid + 256 * j;         // 0..1023 quad index
        tl[j] = (idx >> 3) & 63;               // local t row
        m[j]  = (idx & 7) + 8 * (idx >> 9);    // quad within row (0..15)
    }

    auto stage = [&](unsigned tile, int b) {
        const unsigned bw    = tile >> 4;
        const int      tBase = (int)(tile & (NTILE - 1)) * TT;
        const float* __restrict__ inp = in + (size_t)bw * (T_DIM * C_DIM);
        #pragma unroll
        for (int j = 0; j < 4; ++j) {
            const int t = tBase + tl[j];
            if (t < T_DIM) {
                const uint32_t dst = (uint32_t)__cvta_generic_to_shared(
                    &buf[b][tl[j] * PAD + 4 * m[j]]);
                cp_async16(dst, inp + t * C_DIM + 4 * m[j]);
            }
        }
    };

    // Prologue: stage tile 0 into buffer 0.
    {
        const unsigned t0 = s_t[0];
        if (t0 < NTILES) stage(t0, 0);
        cp_commit();
    }

    const int cl = tid >> 3;   // local channel (0..31)
    const int tq = tid & 7;    // t-quad index

    for (int i = 0; ; ++i) {
        const int      cb   = i & 1;
        const unsigned tcur = s_t[cb];
        if (tcur >= NTILES) break;
        const unsigned tnxt = s_t[cb ^ 1];

        // Stage next tile into the other buffer (overlaps with our store phase).
        if (tnxt < NTILES) stage(tnxt, cb ^ 1);
        cp_commit();
        cp_wait1();            // current tile's copies complete
        __syncthreads();       // publish buffer cb to all warps; s_t reads done

        // Grab tile i+2 into the slot we are about to free (published by loop-end barrier).
        if (tid == 0 && tnxt < NTILES) {
            s_t[cb] = atomicAdd(&g_tile_ctr, 1u);
        }

        // ---- Store phase: 4 STG.128 per thread from buffer cb ----
        {
            const int    tBase = (int)(tcur & (NTILE - 1)) * TT;
            float* __restrict__ outp = out + (size_t)(tcur >> 4) * (T_DIM * C_DIM);
            #pragma unroll
            for (int h = 0; h < 2; ++h) {
                const int c = 32 * h + cl;
                const size_t cRow = (size_t)c * T_DIM;
                #pragma unroll
                for (int r = 0; r < 2; ++r) {
                    const int lt = 4 * tq + 32 * r;
                    const int t  = tBase + lt;
                    if (t + 3 < T_DIM) {
                        float4 o;
                        o.x = buf[cb][(lt + 0) * PAD + c];
                        o.y = buf[cb][(lt + 1) * PAD + c];
                        o.z = buf[cb][(lt + 2) * PAD + c];
                        o.w = buf[cb][(lt + 3) * PAD + c];
                        __stcs(reinterpret_cast<float4*>(outp + cRow + t), o);
                    }
                }
            }
        }
        __syncthreads();       // buffer cb free for restaging; s_t[cb] published
    }
}

extern "C" void kernel_launch(void* const* d_in, const int* in_sizes, int n_in,
                              void* d_out, int out_size)
{
    const float* eeg = (const float*)d_in[0];
    float* out = (float*)d_out;

    const long long tail = (long long)out_size - (long long)PATCH_ELEMS;
    int tail_mode = 0;
    if (tail == 1280)     tail_mode = 2;   // int64 tail
    else if (tail >= 640) tail_mode = 1;   // float32 tail (observed case)

    // Maximize smem carveout so 6 CTAs/SM fit (idempotent, cheap).
    cudaFuncSetAttribute(labram_transpose_pipe_kernel,
                         cudaFuncAttributePreferredSharedMemoryCarveout,
                         cudaSharedmemCarveoutMaxShared);

    // Reset the persistent tile counter each launch (graph-capturable memset node).
    void* ctr_addr = nullptr;
    cudaGetSymbolAddress(&ctr_addr, g_tile_ctr);
    cudaMemsetAsync(ctr_addr, 0, sizeof(unsigned int));

    labram_transpose_pipe_kernel<<<GRID, 256>>>(eeg, out, tail_mode);
}

// round 16
// speedup vs baseline: 1.0743x; 1.0743x over previous
#include <cuda_runtime.h>
#include <cuda_bf16.h>
#include <cstdint>

// eeg_input [16, 32, 1000, 64] fp32 -> per (b,w) slab: 64x1000 transpose of 1000x64.
//   out[bw][c*1000 + t] = in[bw][t*64 + c]
// Tail (out_size - PATCH_ELEMS == 640, f32): channel = i/5, time = i%5, i in [0,320).

#define N_BW   512
#define T_DIM  1000
#define C_DIM  64
#define PATCH_ELEMS (N_BW * T_DIM * C_DIM)   // 32,768,000 floats

// Best-measured geometry (R3): 32 channels x 128 time rows, 256 threads,
// smem 128x33 floats = 16.9KB -> 8 CTAs/SM (64 warps).
// STS scalar bank = (lt + 4cq + k) mod 32  -> bijective per warp.
// LDS scalar bank = (4tq + c + k) mod 32   -> bijective per warp.
// Store phase: each channel row receives 512B sequential from one warp.
__global__ __launch_bounds__(256, 8) void labram_transpose_fused_kernel(
    const float* __restrict__ in, float* __restrict__ out, int tail_mode)
{
    __shared__ float tile[128][33];

    const int bw    = blockIdx.z;
    const int tBase = blockIdx.y * 128;
    const int cBase = blockIdx.x * 32;

    const float* __restrict__ inp  = in  + (size_t)bw * (T_DIM * C_DIM);
    float*       __restrict__ outp = out + (size_t)bw * (T_DIM * C_DIM);

    const int tid  = threadIdx.x;
    const int cq   = tid & 7;    // float4 column within 32-c tile (0..7)
    const int tr   = tid >> 3;   // local t row (0..31), rounds add +32
    const bool full = (tBase + 128 <= T_DIM);   // uniform per-CTA branch

    if (full) {
        // ---- Branchless path (7/8 of CTAs) ----
        float4 v[4];
        #pragma unroll
        for (int j = 0; j < 4; ++j) {
            const int t = tBase + tr + 32 * j;
            v[j] = __ldcs(reinterpret_cast<const float4*>(
                              inp + t * C_DIM + cBase + 4 * cq));
        }
        #pragma unroll
        for (int j = 0; j < 4; ++j) {
            const int lt = tr + 32 * j;
            tile[lt][4 * cq + 0] = v[j].x;
            tile[lt][4 * cq + 1] = v[j].y;
            tile[lt][4 * cq + 2] = v[j].z;
            tile[lt][4 * cq + 3] = v[j].w;
        }
        __syncthreads();

        const int c  = tid >> 3;   // local channel (0..31)
        const int tq = tid & 7;    // t-quad index
        const size_t cRow = (size_t)(cBase + c) * T_DIM;
        #pragma unroll
        for (int r = 0; r < 4; ++r) {
            const int lt = 4 * tq + 32 * r;     // local t base (step 4)
            float4 o;
            o.x = tile[lt + 0][c];
            o.y = tile[lt + 1][c];
            o.z = tile[lt + 2][c];
            o.w = tile[lt + 3][c];
            *reinterpret_cast<float4*>(outp + cRow + tBase + lt) = o;
        }
    } else {
        // ---- Tail tile (t in [896, 1000), 104 rows) ----
        float4 v[4];
        bool   p[4];
        #pragma unroll
        for (int j = 0; j < 4; ++j) {
            const int t = tBase + tr + 32 * j;
            p[j] = (t < T_DIM);
            if (p[j]) {
                v[j] = __ldcs(reinterpret_cast<const float4*>(
                                  inp + t * C_DIM + cBase + 4 * cq));
            }
        }
        #pragma unroll
        for (int j = 0; j < 4; ++j) {
            if (p[j]) {
                const int lt = tr + 32 * j;
                tile[lt][4 * cq + 0] = v[j].x;
                tile[lt][4 * cq + 1] = v[j].y;
                tile[lt][4 * cq + 2] = v[j].z;
                tile[lt][4 * cq + 3] = v[j].w;
            }
        }
        __syncthreads();

        const int c  = tid >> 3;
        const int tq = tid & 7;
        const size_t cRow = (size_t)(cBase + c) * T_DIM;
        #pragma unroll
        for (int r = 0; r < 4; ++r) {
            const int lt = 4 * tq + 32 * r;
            const int t  = tBase + lt;
            if (t + 3 < T_DIM) {
                float4 o;
                o.x = tile[lt + 0][c];
                o.y = tile[lt + 1][c];
                o.z = tile[lt + 2][c];
                o.w = tile[lt + 3][c];
                *reinterpret_cast<float4*>(outp + cRow + t) = o;
            }
        }
    }

    // ---- Fused index tail (one CTA only) ----
    if (tail_mode != 0 && blockIdx.x == 0 && blockIdx.y == 0 && blockIdx.z == 0) {
        for (int i = tid; i < 320; i += 256) {
            if (tail_mode == 1) {            // float32-encoded indices
                out[PATCH_ELEMS + i]       = (float)(i / 5);
                out[PATCH_ELEMS + 320 + i] = (float)(i % 5);
            } else {                          // raw int64 indices
                long long* t64 = (long long*)(out + PATCH_ELEMS);
                t64[i]       = (long long)(i / 5);
                t64[320 + i] = (long long)(i % 5);
            }
        }
    }
}

extern "C" void kernel_launch(void* const* d_in, const int* in_sizes, int n_in,
                              void* d_out, int out_size)
{
    const float* eeg = (const float*)d_in[0];
    float* out = (float*)d_out;

    const long long tail = (long long)out_size - (long long)PATCH_ELEMS;
    int tail_mode = 0;
    if (tail == 1280)     tail_mode = 2;   // int64 tail
    else if (tail >= 640) tail_mode = 1;   // float32 tail (observed case)

    dim3 block(256);
    dim3 grid(C_DIM / 32,                    // 2 channel tiles
              (T_DIM + 127) / 128,           // 8 time tiles (last partial: 104)
              N_BW);                         // 512 batches
    labram_transpose_fused_kernel<<<grid, block>>>(eeg, out, tail_mode);
}